// round 3
// baseline (speedup 1.0000x reference)
#include <cuda_runtime.h>
#include <cuda_fp16.h>
#include <cstdint>

// Problem constants (fixed by the dataset)
#define NCH   12
#define GD    160
#define GH    160
#define GW    160
#define GVOL  (GD * GH * GW)          // 4,096,000 voxels

// Split channel-last fp16 scratch (total 98.3 MB, fits GB300 ~126 MB L2):
//   g_A: channels 0-7,  16 B/voxel, 16B-aligned -> pair (x0,x0+1) = 2x LDG.128
//   g_B: channels 8-11,  8 B/voxel,  8B-aligned -> pair = 2x LDG.64
// +1 voxel of zero padding so the x0+1 load at the last voxel stays in-bounds
// (its weight fx is exactly 0 there, and 0-init padding can't produce NaN).
__device__ __align__(16) __half g_A[((size_t)GVOL + 4) * 8];
__device__ __align__(16) __half g_B[((size_t)GVOL + 4) * 4];

// ---------------------------------------------------------------------------
// Pass 1: transpose+convert [C, D, H, W] fp32 -> split channel-last fp16.
// fp32 reads use __ldcs (evict-first) so they do NOT evict the fp16 writes
// from L2 -> the 98 MB fp16 grid is L2-resident when the sample pass starts.
// ---------------------------------------------------------------------------
__global__ void __launch_bounds__(256) convert_cl_kernel(const float* __restrict__ grid) {
    int v = blockIdx.x * blockDim.x + threadIdx.x;
    if (v >= GVOL) return;

    __half hA[8];
    __half hB[4];
#pragma unroll
    for (int c = 0; c < 8; c++)
        hA[c] = __float2half(__ldcs(grid + (size_t)c * GVOL + v));
#pragma unroll
    for (int c = 0; c < 4; c++)
        hB[c] = __float2half(__ldcs(grid + (size_t)(8 + c) * GVOL + v));

    *reinterpret_cast<uint4*>(g_A + (size_t)v * 8) = *reinterpret_cast<const uint4*>(hA);
    *reinterpret_cast<uint2*>(g_B + (size_t)v * 4) = *reinterpret_cast<const uint2*>(hB);
}

// ---------------------------------------------------------------------------
// Pass 2: trilinear sample, one thread per point, all 12 channels.
// 16 gather loads per point (8x LDG.128 + 8x LDG.64) instead of 24x LDG.64.
// ---------------------------------------------------------------------------
__device__ __forceinline__ float2 u2f2(unsigned u) {
    __half2 h = *reinterpret_cast<__half2*>(&u);
    return __half22float2(h);
}

__global__ void __launch_bounds__(256) trilinear_sample_kernel(
    const float* __restrict__ xyz,
    const float* __restrict__ xyz_min,
    const float* __restrict__ xyz_max,
    float* __restrict__ out,
    int n)
{
    int i = blockIdx.x * blockDim.x + threadIdx.x;
    if (i >= n) return;

    float p0 = __ldcs(xyz + 3 * (size_t)i + 0);
    float p1 = __ldcs(xyz + 3 * (size_t)i + 1);
    float p2 = __ldcs(xyz + 3 * (size_t)i + 2);

    float mn0 = __ldg(xyz_min + 0), mn1 = __ldg(xyz_min + 1), mn2 = __ldg(xyz_min + 2);
    float mx0 = __ldg(xyz_max + 0), mx1 = __ldg(xyz_max + 1), mx2 = __ldg(xyz_max + 2);

    float u0 = (p0 - mn0) / (mx0 - mn0);
    float u1 = (p1 - mn1) / (mx1 - mn1);
    float u2 = (p2 - mn2) / (mx2 - mn2);

    // px indexes W (from u2), py indexes H (from u1), pz indexes D (from u0)
    float px = u2 * (float)(GW - 1);
    float py = u1 * (float)(GH - 1);
    float pz = u0 * (float)(GD - 1);

    float xf = floorf(px), yf = floorf(py), zf = floorf(pz);
    float fx = px - xf,    fy = py - yf,    fz = pz - zf;

    int x0 = min(max((int)xf, 0), GW - 1);
    int y0 = min(max((int)yf, 0), GH - 1);
    int z0 = min(max((int)zf, 0), GD - 1);
    int y1 = min(y0 + 1, GH - 1);
    int z1 = min(z0 + 1, GD - 1);

    float wx0 = 1.0f - fx, wx1 = fx;
    float wy0 = 1.0f - fy, wy1 = fy;
    float wz0 = 1.0f - fz, wz1 = fz;

    float wp[4];
    wp[0] = wz0 * wy0;
    wp[1] = wz0 * wy1;
    wp[2] = wz1 * wy0;
    wp[3] = wz1 * wy1;

    int vidx[4];
    vidx[0] = (z0 * GH + y0) * GW + x0;
    vidx[1] = (z0 * GH + y1) * GW + x0;
    vidx[2] = (z1 * GH + y0) * GW + x0;
    vidx[3] = (z1 * GH + y1) * GW + x0;

    float acc[NCH];
#pragma unroll
    for (int c = 0; c < NCH; c++) acc[c] = 0.0f;

#pragma unroll
    for (int p = 0; p < 4; p++) {
        const uint4* pA = reinterpret_cast<const uint4*>(g_A + (size_t)vidx[p] * 8);
        const uint2* pB = reinterpret_cast<const uint2*>(g_B + (size_t)vidx[p] * 4);

        uint4 A0 = __ldg(pA + 0);   // ch0-7 of x0
        uint4 A1 = __ldg(pA + 1);   // ch0-7 of x0+1
        uint2 B0 = __ldg(pB + 0);   // ch8-11 of x0
        uint2 B1 = __ldg(pB + 1);   // ch8-11 of x0+1

        float w0 = wp[p] * wx0;
        float w1 = wp[p] * wx1;

        float2 a, b;
        a = u2f2(A0.x); b = u2f2(A1.x);
        acc[0]  = fmaf(w0, a.x, fmaf(w1, b.x, acc[0]));
        acc[1]  = fmaf(w0, a.y, fmaf(w1, b.y, acc[1]));
        a = u2f2(A0.y); b = u2f2(A1.y);
        acc[2]  = fmaf(w0, a.x, fmaf(w1, b.x, acc[2]));
        acc[3]  = fmaf(w0, a.y, fmaf(w1, b.y, acc[3]));
        a = u2f2(A0.z); b = u2f2(A1.z);
        acc[4]  = fmaf(w0, a.x, fmaf(w1, b.x, acc[4]));
        acc[5]  = fmaf(w0, a.y, fmaf(w1, b.y, acc[5]));
        a = u2f2(A0.w); b = u2f2(A1.w);
        acc[6]  = fmaf(w0, a.x, fmaf(w1, b.x, acc[6]));
        acc[7]  = fmaf(w0, a.y, fmaf(w1, b.y, acc[7]));
        a = u2f2(B0.x); b = u2f2(B1.x);
        acc[8]  = fmaf(w0, a.x, fmaf(w1, b.x, acc[8]));
        acc[9]  = fmaf(w0, a.y, fmaf(w1, b.y, acc[9]));
        a = u2f2(B0.y); b = u2f2(B1.y);
        acc[10] = fmaf(w0, a.x, fmaf(w1, b.x, acc[10]));
        acc[11] = fmaf(w0, a.y, fmaf(w1, b.y, acc[11]));
    }

    // out is [N, 12] row-major; 48B per thread -> 3x float4 streaming stores
    float4* o = reinterpret_cast<float4*>(out + (size_t)i * NCH);
    __stcs(o + 0, make_float4(acc[0], acc[1], acc[2],  acc[3]));
    __stcs(o + 1, make_float4(acc[4], acc[5], acc[6],  acc[7]));
    __stcs(o + 2, make_float4(acc[8], acc[9], acc[10], acc[11]));
}

extern "C" void kernel_launch(void* const* d_in, const int* in_sizes, int n_in,
                              void* d_out, int out_size) {
    const float* xyz     = (const float*)d_in[0];  // [N, 3]
    const float* grid    = (const float*)d_in[1];  // [1, 12, 160, 160, 160]
    const float* xyz_min = (const float*)d_in[2];  // [3]
    const float* xyz_max = (const float*)d_in[3];  // [3]
    float* out = (float*)d_out;                    // [N, 12]

    int n = in_sizes[0] / 3;

    {
        int threads = 256;
        int blocks = (GVOL + threads - 1) / threads;
        convert_cl_kernel<<<blocks, threads>>>(grid);
    }
    {
        int threads = 256;
        int blocks = (n + threads - 1) / threads;
        trilinear_sample_kernel<<<blocks, threads>>>(xyz, xyz_min, xyz_max, out, n);
    }
}